// round 13
// baseline (speedup 1.0000x reference)
#include <cuda_runtime.h>
#include <math.h>

#define B 32
#define H 512
#define W 512
#define C4 (W / 4)          // 128 float4 per row
#define KS 31
#define PAD 15
#define IMG4 (H * C4)
#define RS 8                // rows per warp-strip
#define SPI (H / RS)        // 64 strips per image
#define NWARPS (B * SPI)    // 2048

__device__ float4 g_part[NWARPS];   // {wsum, wbce_num, inter, union} per warp
__device__ unsigned int g_ctr;      // zero-init; last warp resets (graph replay)

__inline__ __device__ float warp_reduce(float v) {
    #pragma unroll
    for (int o = 16; o > 0; o >>= 1) v += __shfl_down_sync(0xffffffffu, v, o);
    return v;
}

__inline__ __device__ float4 f4add(float4 a, float4 b) {
    return make_float4(a.x + b.x, a.y + b.y, a.z + b.z, a.w + b.w);
}
__inline__ __device__ float4 f4sub(float4 a, float4 b) {
    return make_float4(a.x - b.x, a.y - b.y, a.z - b.z, a.w - b.w);
}
__inline__ __device__ float comp(float4 v, int k) {
    return k == 0 ? v.x : k == 1 ? v.y : k == 2 ? v.z : v.w;
}

// One warp processes a strip: rows [r0, r0+RS) x all 512 columns.
// Thread 'lane' owns columns [16*lane, 16*lane+16) = float4 indices 4*lane..4*lane+3.
template <bool INTERIOR>
__device__ __forceinline__ void run_strip(
    const float4* __restrict__ t,   // image base + 4*lane
    const float4* __restrict__ p,   // image base + 4*lane
    int r0, int lane,
    float& acc0, float& acc1, float& acc2, float& acc3)
{
    const float4 z4 = make_float4(0.f, 0.f, 0.f, 0.f);
    const float inv = 1.0f / (KS * KS);

    // ---- preamble: vertical window = rows [r0-15, r0+14] (clamped) ----
    float4 v0 = z4, v1 = z4, v2 = z4, v3 = z4;
    if (INTERIOR) {
        const float4* tb = t + (r0 - PAD) * C4;
        #pragma unroll 3
        for (int h = 0; h < 2 * PAD; ++h) {
            v0 = f4add(v0, tb[0]); v1 = f4add(v1, tb[1]);
            v2 = f4add(v2, tb[2]); v3 = f4add(v3, tb[3]);
            tb += C4;
        }
    } else {
        int hlo = r0 - PAD; if (hlo < 0) hlo = 0;
        int hhi = r0 + PAD; if (hhi > H) hhi = H;
        const float4* tb = t + hlo * C4;
        for (int h = hlo; h < hhi; ++h) {
            v0 = f4add(v0, tb[0]); v1 = f4add(v1, tb[1]);
            v2 = f4add(v2, tb[2]); v3 = f4add(v3, tb[3]);
            tb += C4;
        }
    }

    const float4* tadd = t + (r0 + PAD) * C4;
    const float4* tsub = t + (r0 - PAD) * C4;
    const float4* trow = t + r0 * C4;
    const float4* prow = p + r0 * C4;

    for (int i = 0; i < RS; ++i) {
        const int r = r0 + i;

        // ---- loads for this row (batched for MLP) ----
        float4 a0, a1, a2, a3, s0, s1, s2, s3;
        if (INTERIOR || (r + PAD < H)) {
            a0 = tadd[0]; a1 = tadd[1]; a2 = tadd[2]; a3 = tadd[3];
        } else { a0 = a1 = a2 = a3 = z4; }
        if (INTERIOR || (r - PAD >= 0)) {
            s0 = tsub[0]; s1 = tsub[1]; s2 = tsub[2]; s3 = tsub[3];
        } else { s0 = s1 = s2 = s3 = z4; }
        const float4 tg0 = trow[0], tg1 = trow[1], tg2 = trow[2], tg3 = trow[3];
        const float4 x0  = prow[0], x1  = prow[1], x2  = prow[2], x3  = prow[3];

        // ---- vertical window sum for row r ----
        v0 = f4add(v0, a0); v1 = f4add(v1, a1);
        v2 = f4add(v2, a2); v3 = f4add(v3, a3);

        // thread-local inclusive prefix over 16 columns
        float P[16];
        P[0]  = v0.x;         P[1]  = P[0]  + v0.y;
        P[2]  = P[1]  + v0.z; P[3]  = P[2]  + v0.w;
        P[4]  = P[3]  + v1.x; P[5]  = P[4]  + v1.y;
        P[6]  = P[5]  + v1.z; P[7]  = P[6]  + v1.w;
        P[8]  = P[7]  + v2.x; P[9]  = P[8]  + v2.y;
        P[10] = P[9]  + v2.z; P[11] = P[10] + v2.w;
        P[12] = P[11] + v3.x; P[13] = P[12] + v3.y;
        P[14] = P[13] + v3.z; P[15] = P[14] + v3.w;

        // retire window for next row (independent of scan chain)
        v0 = f4sub(v0, s0); v1 = f4sub(v1, s1);
        v2 = f4sub(v2, s2); v3 = f4sub(v3, s3);

        // warp inclusive scan of thread totals
        const float tot = P[15];
        float incl = tot;
        #pragma unroll
        for (int o = 1; o < 32; o <<= 1) {
            const float n = __shfl_up_sync(0xffffffffu, incl, o);
            if (lane >= o) incl += n;
        }
        const float base = incl - tot;
        #pragma unroll
        for (int k = 0; k < 16; ++k) P[k] += base;   // global prefix P[16*lane+k]

        // ---- taps via lane shuffles + elementwise loss ----
        #pragma unroll
        for (int q = 0; q < 4; ++q) {
            const float4 tg = (q == 0) ? tg0 : (q == 1) ? tg1 : (q == 2) ? tg2 : tg3;
            const float4 xx = (q == 0) ? x0  : (q == 1) ? x1  : (q == 2) ? x2  : x3;
            #pragma unroll
            for (int m = 0; m < 4; ++m) {
                const int k = 4 * q + m;
                // hi = P[c+15]: own P[15] for k=0, else next lane's P[k-1]
                float hi;
                if (k == 0) {
                    hi = P[15];
                } else {
                    hi = __shfl_down_sync(0xffffffffu, P[k - 1], 1);
                    if (lane == 31) hi = P[15];     // clamp: P[>=512] = P[511]
                }
                // lo = P[c-16]: prev lane's P[k]; lane 0 -> 0 (zero pad)
                float lo = __shfl_up_sync(0xffffffffu, P[k], 1);
                if (lane == 0) lo = 0.f;

                const float box  = (hi - lo) * inv;
                const float tgv  = comp(tg, m);
                const float xv   = comp(xx, m);

                const float weit = fmaf(5.f, fabsf(box - tgv), 1.f);
                // exact: max(x,0) + log1p(e^{-|x|}) = x + log1p(e^{-x})
                const float u   = __expf(-xv);
                const float vv  = 1.f + u;
                const float lg  = __logf(vv);
                const float bce = fmaf(-xv, tgv, lg + xv);
                const float pr  = __fdividef(1.f, vv);   // sigmoid(x)

                acc0 += weit;
                acc1 = fmaf(weit, bce, acc1);
                acc2 = fmaf(pr * tgv, weit, acc2);
                acc3 = fmaf(pr + tgv, weit, acc3);
            }
        }

        tadd += C4; tsub += C4; trow += C4; prow += C4;
    }
}

__global__ void __launch_bounds__(32, 16)
fused_loss_warp(const float4* __restrict__ pred,
                const float4* __restrict__ target,
                float* __restrict__ out)
{
    const int strip = blockIdx.x;   // 0..SPI-1
    const int b     = blockIdx.y;   // image
    const int lane  = threadIdx.x;  // 0..31
    const int r0    = strip * RS;

    const float4* t = target + b * IMG4 + 4 * lane;
    const float4* p = pred   + b * IMG4 + 4 * lane;

    float acc0 = 0.f, acc1 = 0.f, acc2 = 0.f, acc3 = 0.f;

    // interior: preamble row r0-15 >= 0 and deepest add row r0+RS-1+15 <= H-1
    if (r0 >= 16 && r0 <= H - RS - PAD - 1) {
        run_strip<true>(t, p, r0, lane, acc0, acc1, acc2, acc3);
    } else {
        run_strip<false>(t, p, r0, lane, acc0, acc1, acc2, acc3);
    }

    // ---- warp reduction of 4 accumulators ----
    acc0 = warp_reduce(acc0);
    acc1 = warp_reduce(acc1);
    acc2 = warp_reduce(acc2);
    acc3 = warp_reduce(acc3);

    const int wgid = b * SPI + strip;
    if (lane == 0) {
        g_part[wgid] = make_float4(acc0, acc1, acc2, acc3);
        __threadfence();
    }
    __syncwarp();

    unsigned int ticket = 0;
    if (lane == 0) ticket = atomicAdd(&g_ctr, 1u);
    ticket = __shfl_sync(0xffffffffu, ticket, 0);
    if (ticket == NWARPS - 1) {
        // lane = image index
        float wsum = 0.f, wbce_n = 0.f, inter = 0.f, uni = 0.f;
        const float4* gp = g_part + lane * SPI;
        #pragma unroll 8
        for (int s = 0; s < SPI; ++s) {
            const float4 v = gp[s];
            wsum   += v.x;
            wbce_n += v.y;
            inter  += v.z;
            uni    += v.w;
        }
        const float wbce = wbce_n / wsum;
        const float wiou = 1.0f - (inter + 1.0f) / (uni - inter + 1.0f);
        float loss = warp_reduce(wbce + wiou);
        if (lane == 0) {
            out[0] = loss * (1.0f / B);
            g_ctr = 0;   // reset for graph replay
        }
    }
}

extern "C" void kernel_launch(void* const* d_in, const int* in_sizes, int n_in,
                              void* d_out, int out_size) {
    const float4* pred   = (const float4*)d_in[0];
    const float4* target = (const float4*)d_in[1];
    float* out = (float*)d_out;

    dim3 grid(SPI, B);
    fused_loss_warp<<<grid, 32>>>(pred, target, out);
}

// round 14
// speedup vs baseline: 1.4792x; 1.4792x over previous
#include <cuda_runtime.h>
#include <math.h>

#define B 32
#define H 512
#define W 512
#define C4 (W / 4)
#define KS 31
#define PAD 15
#define IMG4 (H * C4)
#define STRIPS 32
#define ROWS (H / STRIPS)      // 16
#define ROUNDS (ROWS / 2)      // 8
#define NBLOCKS (B * STRIPS)   // 1024

__device__ float g_part[NBLOCKS * 4];
__device__ unsigned int g_ctr;

__inline__ __device__ float warp_reduce(float v) {
    #pragma unroll
    for (int o = 16; o > 0; o >>= 1) v += __shfl_down_sync(0xffffffffu, v, o);
    return v;
}

__inline__ __device__ void warp_iscan2(float& a, float& b, int lane) {
    #pragma unroll
    for (int o = 1; o < 32; o <<= 1) {
        const float na = __shfl_up_sync(0xffffffffu, a, o);
        const float nb = __shfl_up_sync(0xffffffffu, b, o);
        if (lane >= o) { a += na; b += nb; }
    }
}

__inline__ __device__ float4 f4add(float4 a, float4 b) {
    return make_float4(a.x + b.x, a.y + b.y, a.z + b.z, a.w + b.w);
}
__inline__ __device__ float4 f4sub(float4 a, float4 b) {
    return make_float4(a.x - b.x, a.y - b.y, a.z - b.z, a.w - b.w);
}

template <bool INTERIOR>
__device__ __forceinline__ void run_strip(
    const float4* __restrict__ t, const float4* __restrict__ p,
    int r0, int w, int lane, int wid,
    float4 (*sP)[2][136], float2 (*s_warp)[4],
    float& acc0, float& acc1, float& acc2, float& acc3)
{
    const float4 zero4 = make_float4(0.f, 0.f, 0.f, 0.f);
    const float invf = 1.0f / (KS * KS);

    // ---- preamble vertical window: rows [r0-15, r0+14] (clamped) ----
    float4 sA = zero4, sB = zero4;
    if (INTERIOR) {
        const float4* tb = t + (r0 - PAD) * C4 + w;
        #pragma unroll
        for (int h = 0; h < 2 * PAD; h += 2) {
            sA = f4add(sA, tb[h * C4]);
            sB = f4add(sB, tb[(h + 1) * C4]);
        }
    } else {
        int hlo = r0 - PAD; if (hlo < 0) hlo = 0;
        int hhi = r0 + PAD; if (hhi > H) hhi = H;
        int h = hlo;
        for (; h + 1 < hhi; h += 2) {
            sA = f4add(sA, t[h * C4 + w]);
            sB = f4add(sB, t[(h + 1) * C4 + w]);
        }
        if (h < hhi) sA = f4add(sA, t[h * C4 + w]);
    }
    float4 sum4 = f4add(sA, sB);

    const float4* tc = t + r0 * C4 + w;
    const float4* pc = p + r0 * C4 + w;

    // prefetch round-0 tg/x
    float4 tg0 = tc[0];
    float4 tg1 = tc[C4];
    float4 x0  = pc[0];
    float4 x1  = pc[C4];

    for (int g = 0; g < ROUNDS; ++g) {
        const int r   = r0 + 2 * g;
        const int buf = g & 1;

        float4 a0, a1, s0, s1;
        if (INTERIOR) {
            a0 = tc[15 * C4];
            a1 = tc[16 * C4];
            s0 = tc[-15 * C4];
            s1 = tc[-14 * C4];
        } else {
            a0 = (r + PAD < H)      ? tc[15 * C4]  : zero4;
            a1 = (r + 1 + PAD < H)  ? tc[16 * C4]  : zero4;
            s0 = (r - PAD >= 0)     ? tc[-15 * C4] : zero4;
            s1 = (r + 1 - PAD >= 0) ? tc[-14 * C4] : zero4;
        }

        sum4 = f4add(sum4, a0);
        const float4 vs0 = sum4;
        sum4 = f4sub(sum4, s0);
        sum4 = f4add(sum4, a1);
        const float4 vs1 = sum4;
        sum4 = f4sub(sum4, s1);

        const float q0a = vs0.x, q1a = q0a + vs0.y, q2a = q1a + vs0.z, q3a = q2a + vs0.w;
        const float q0b = vs1.x, q1b = q0b + vs1.y, q2b = q1b + vs1.z, q3b = q2b + vs1.w;

        float ia = q3a, ib = q3b;
        warp_iscan2(ia, ib, lane);
        const float exa = ia - q3a;
        const float exb = ib - q3b;
        if (lane == 31) s_warp[buf][wid] = make_float2(ia, ib);
        __syncthreads();   // BAR_a

        const float2 W0 = s_warp[buf][0];
        const float2 W1 = s_warp[buf][1];
        const float2 W2 = s_warp[buf][2];
        const float2 W3 = s_warp[buf][3];

        const float offa = (wid > 0 ? W0.x : 0.f) + (wid > 1 ? W1.x : 0.f) + (wid > 2 ? W2.x : 0.f);
        const float offb = (wid > 0 ? W0.y : 0.f) + (wid > 1 ? W1.y : 0.f) + (wid > 2 ? W2.y : 0.f);
        const float basea = offa + exa;
        const float baseb = offb + exb;

        sP[buf][0][w + 4] = make_float4(basea + q0a, basea + q1a, basea + q2a, basea + q3a);
        sP[buf][1][w + 4] = make_float4(baseb + q0b, baseb + q1b, baseb + q2b, baseb + q3b);
        if (w < 4) {
            const float tota = W0.x + W1.x + W2.x + W3.x;
            const float totb = W0.y + W1.y + W2.y + W3.y;
            sP[buf][0][132 + w] = make_float4(tota, tota, tota, tota);
            sP[buf][1][132 + w] = make_float4(totb, totb, totb, totb);
        }
        __syncthreads();   // BAR_b

        // ---- prefetch next round's tg/x (independent; lands during next round) ----
        float4 ntg0, ntg1, nx0, nx1;
        if (g + 1 < ROUNDS) {
            ntg0 = tc[2 * C4];
            ntg1 = tc[3 * C4];
            nx0  = pc[2 * C4];
            nx1  = pc[3 * C4];
        } else {
            ntg0 = ntg1 = nx0 = nx1 = zero4;
        }

        // ---- taps + elementwise loss for both rows (uses prefetched tg/x) ----
        #pragma unroll
        for (int j = 0; j < 2; ++j) {
            const float4 tg = j ? tg1 : tg0;
            const float4 xq = j ? x1 : x0;
            const float4 lo = sP[buf][j][w];
            const float4 A  = sP[buf][j][w + 7];
            const float4 Bv = sP[buf][j][w + 8];

            const float hi[4]  = {A.w, Bv.x, Bv.y, Bv.z};
            const float lov[4] = {lo.x, lo.y, lo.z, lo.w};
            const float tgv[4] = {tg.x, tg.y, tg.z, tg.w};
            const float xv[4]  = {xq.x, xq.y, xq.z, xq.w};

            #pragma unroll
            for (int k = 0; k < 4; ++k) {
                const float box  = (hi[k] - lov[k]) * invf;
                const float weit = fmaf(5.f, fabsf(box - tgv[k]), 1.f);

                // exact: max(x,0) + log1p(e^{-|x|}) = x + log1p(e^{-x})
                const float u   = __expf(-xv[k]);
                const float v   = 1.f + u;
                const float lg  = __logf(v);
                const float bce = fmaf(-xv[k], tgv[k], lg + xv[k]);
                const float pr  = __fdividef(1.f, v);   // sigmoid(x)

                acc0 += weit;
                acc1 = fmaf(weit, bce, acc1);
                acc2 = fmaf(pr * tgv[k], weit, acc2);
                acc3 = fmaf(pr + tgv[k], weit, acc3);
            }
        }

        tg0 = ntg0; tg1 = ntg1; x0 = nx0; x1 = nx1;
        tc += 2 * C4;
        pc += 2 * C4;
    }
}

__global__ void __launch_bounds__(128, 7)
fused_loss_kernel(const float4* __restrict__ pred,
                  const float4* __restrict__ target,
                  float* __restrict__ out) {
    const int strip = blockIdx.x;
    const int b     = blockIdx.y;
    const int w     = threadIdx.x;
    const int lane  = w & 31;
    const int wid   = w >> 5;
    const int r0    = strip * ROWS;

    const float4* t = target + b * IMG4;
    const float4* p = pred   + b * IMG4;

    __shared__ float4 sP[2][2][136];
    __shared__ float2 s_warp[2][4];
    __shared__ float  s_red[4][4];

    if (w < 16) sP[(w >> 3) & 1][(w >> 2) & 1][w & 3] = make_float4(0.f, 0.f, 0.f, 0.f);

    float acc0 = 0.f, acc1 = 0.f, acc2 = 0.f, acc3 = 0.f;

    if (strip >= 1 && strip <= STRIPS - 2) {
        run_strip<true>(t, p, r0, w, lane, wid, sP, s_warp, acc0, acc1, acc2, acc3);
    } else {
        run_strip<false>(t, p, r0, w, lane, wid, sP, s_warp, acc0, acc1, acc2, acc3);
    }

    // ---- block reduction (4 warps) ----
    float vals[4] = {acc0, acc1, acc2, acc3};
    #pragma unroll
    for (int k = 0; k < 4; ++k) {
        const float v = warp_reduce(vals[k]);
        if (lane == 0) s_red[k][wid] = v;
    }
    __syncthreads();

    if (wid == 0) {
        float v[4];
        #pragma unroll
        for (int k = 0; k < 4; ++k) {
            float vv = (lane < 4) ? s_red[k][lane] : 0.f;
            #pragma unroll
            for (int o = 2; o > 0; o >>= 1) vv += __shfl_down_sync(0xffffffffu, vv, o);
            v[k] = vv;
        }
        if (lane == 0) {
            #pragma unroll
            for (int k = 0; k < 4; ++k)
                g_part[(b * STRIPS + strip) * 4 + k] = v[k];
            __threadfence();
        }
        __syncwarp();

        unsigned int ticket = 0;
        if (lane == 0) ticket = atomicAdd(&g_ctr, 1u);
        ticket = __shfl_sync(0xffffffffu, ticket, 0);
        if (ticket == NBLOCKS - 1) {
            float wsum = 0.f, wbce_n = 0.f, inter = 0.f, uni = 0.f;
            #pragma unroll 4
            for (int s = 0; s < STRIPS; ++s) {
                const float* pp = &g_part[(lane * STRIPS + s) * 4];
                wsum   += pp[0];
                wbce_n += pp[1];
                inter  += pp[2];
                uni    += pp[3];
            }
            const float wbce = wbce_n / wsum;
            const float wiou = 1.0f - (inter + 1.0f) / (uni - inter + 1.0f);
            float loss = warp_reduce(wbce + wiou);
            if (lane == 0) {
                out[0] = loss * (1.0f / B);
                g_ctr = 0;
            }
        }
    }
}

extern "C" void kernel_launch(void* const* d_in, const int* in_sizes, int n_in,
                              void* d_out, int out_size) {
    const float4* pred   = (const float4*)d_in[0];
    const float4* target = (const float4*)d_in[1];
    float* out = (float*)d_out;

    dim3 grid(STRIPS, B);
    fused_loss_kernel<<<grid, 128>>>(pred, target, out);
}

// round 15
// speedup vs baseline: 1.5867x; 1.0727x over previous
#include <cuda_runtime.h>
#include <math.h>

#define B 32
#define H 512
#define W 512
#define C4 (W / 4)
#define KS 31
#define PAD 15
#define IMG4 (H * C4)
#define STRIPS 32
#define ROWS (H / STRIPS)      // 16
#define ROUNDS (ROWS / 2)      // 8
#define NBLOCKS (B * STRIPS)   // 1024

__device__ float g_part[NBLOCKS * 4];
__device__ unsigned int g_ctr;

__inline__ __device__ float warp_reduce(float v) {
    #pragma unroll
    for (int o = 16; o > 0; o >>= 1) v += __shfl_down_sync(0xffffffffu, v, o);
    return v;
}

__inline__ __device__ void warp_iscan2(float& a, float& b, int lane) {
    #pragma unroll
    for (int o = 1; o < 32; o <<= 1) {
        const float na = __shfl_up_sync(0xffffffffu, a, o);
        const float nb = __shfl_up_sync(0xffffffffu, b, o);
        if (lane >= o) { a += na; b += nb; }
    }
}

__inline__ __device__ float4 f4add(float4 a, float4 b) {
    return make_float4(a.x + b.x, a.y + b.y, a.z + b.z, a.w + b.w);
}
__inline__ __device__ float4 f4sub(float4 a, float4 b) {
    return make_float4(a.x - b.x, a.y - b.y, a.z - b.z, a.w - b.w);
}

__inline__ __device__ float tanh_approx(float x) {
    float r; asm("tanh.approx.f32 %0, %1;" : "=f"(r) : "f"(x)); return r;
}

template <bool INTERIOR>
__device__ __forceinline__ void run_strip(
    const float4* __restrict__ t, const float4* __restrict__ p,
    int r0, int w, int lane, int wid,
    float4 (*sP)[2][136], float2 (*s_warp)[4],
    float& acc0, float& acc1, float& acc2, float& acc3)
{
    const float4 zero4 = make_float4(0.f, 0.f, 0.f, 0.f);
    const float invf = 1.0f / (KS * KS);

    // ---- preamble vertical window: rows [r0-15, r0+14] (clamped) ----
    float4 sA = zero4, sB = zero4;
    if (INTERIOR) {
        const float4* tb = t + (r0 - PAD) * C4 + w;
        #pragma unroll
        for (int h = 0; h < 2 * PAD; h += 2) {
            sA = f4add(sA, tb[h * C4]);
            sB = f4add(sB, tb[(h + 1) * C4]);
        }
    } else {
        int hlo = r0 - PAD; if (hlo < 0) hlo = 0;
        int hhi = r0 + PAD; if (hhi > H) hhi = H;
        int h = hlo;
        for (; h + 1 < hhi; h += 2) {
            sA = f4add(sA, t[h * C4 + w]);
            sB = f4add(sB, t[(h + 1) * C4 + w]);
        }
        if (h < hhi) sA = f4add(sA, t[h * C4 + w]);
    }
    float4 sum4 = f4add(sA, sB);

    const float4* tc = t + r0 * C4 + w;
    const float4* pc = p + r0 * C4 + w;

    for (int g = 0; g < ROUNDS; ++g) {
        const int r   = r0 + 2 * g;
        const int buf = g & 1;

        float4 a0, a1, s0, s1;
        if (INTERIOR) {
            a0 = tc[15 * C4];
            a1 = tc[16 * C4];
            s0 = tc[-15 * C4];
            s1 = tc[-14 * C4];
        } else {
            a0 = (r + PAD < H)      ? tc[15 * C4]  : zero4;
            a1 = (r + 1 + PAD < H)  ? tc[16 * C4]  : zero4;
            s0 = (r - PAD >= 0)     ? tc[-15 * C4] : zero4;
            s1 = (r + 1 - PAD >= 0) ? tc[-14 * C4] : zero4;
        }

        sum4 = f4add(sum4, a0);
        const float4 vs0 = sum4;
        sum4 = f4sub(sum4, s0);
        sum4 = f4add(sum4, a1);
        const float4 vs1 = sum4;
        sum4 = f4sub(sum4, s1);

        const float q0a = vs0.x, q1a = q0a + vs0.y, q2a = q1a + vs0.z, q3a = q2a + vs0.w;
        const float q0b = vs1.x, q1b = q0b + vs1.y, q2b = q1b + vs1.z, q3b = q2b + vs1.w;

        float ia = q3a, ib = q3b;
        warp_iscan2(ia, ib, lane);
        const float exa = ia - q3a;
        const float exb = ib - q3b;
        if (lane == 31) s_warp[buf][wid] = make_float2(ia, ib);
        __syncthreads();   // BAR_a

        const float2 W0 = s_warp[buf][0];
        const float2 W1 = s_warp[buf][1];
        const float2 W2 = s_warp[buf][2];
        const float2 W3 = s_warp[buf][3];

        const float offa = (wid > 0 ? W0.x : 0.f) + (wid > 1 ? W1.x : 0.f) + (wid > 2 ? W2.x : 0.f);
        const float offb = (wid > 0 ? W0.y : 0.f) + (wid > 1 ? W1.y : 0.f) + (wid > 2 ? W2.y : 0.f);
        const float basea = offa + exa;
        const float baseb = offb + exb;

        sP[buf][0][w + 4] = make_float4(basea + q0a, basea + q1a, basea + q2a, basea + q3a);
        sP[buf][1][w + 4] = make_float4(baseb + q0b, baseb + q1b, baseb + q2b, baseb + q3b);
        if (w < 4) {
            const float tota = W0.x + W1.x + W2.x + W3.x;
            const float totb = W0.y + W1.y + W2.y + W3.y;
            sP[buf][0][132 + w] = make_float4(tota, tota, tota, tota);
            sP[buf][1][132 + w] = make_float4(totb, totb, totb, totb);
        }
        __syncthreads();   // BAR_b

        // tg/x loaded here: short live range; rows are L1/L2-warm.
        #pragma unroll
        for (int j = 0; j < 2; ++j) {
            const float4 tg = j ? tc[C4] : tc[0];
            const float4 xq = j ? pc[C4] : pc[0];
            const float4 lo = sP[buf][j][w];
            const float4 A  = sP[buf][j][w + 7];
            const float4 Bv = sP[buf][j][w + 8];

            const float hi[4]  = {A.w, Bv.x, Bv.y, Bv.z};
            const float lov[4] = {lo.x, lo.y, lo.z, lo.w};
            const float tgv[4] = {tg.x, tg.y, tg.z, tg.w};
            const float xv[4]  = {xq.x, xq.y, xq.z, xq.w};

            #pragma unroll
            for (int k = 0; k < 4; ++k) {
                const float box  = (hi[k] - lov[k]) * invf;
                const float weit = fmaf(5.f, fabsf(box - tgv[k]), 1.f);

                // sigmoid via single MUFU.TANH; BCE log via -log(p):
                //   p = 0.5*tanh(x/2) + 0.5
                //   max(x,0)+log1p(e^{-|x|}) - x*t = x*(1-t) - log(p)
                const float ph  = tanh_approx(0.5f * xv[k]);
                const float pr  = fmaf(0.5f, ph, 0.5f);
                const float lg  = __logf(pr);
                const float bce = fmaf(xv[k], 1.f - tgv[k], -lg);

                acc0 += weit;
                acc1 = fmaf(weit, bce, acc1);
                acc2 = fmaf(pr * tgv[k], weit, acc2);
                acc3 = fmaf(pr + tgv[k], weit, acc3);
            }
        }

        tc += 2 * C4;
        pc += 2 * C4;
    }
}

__global__ void __launch_bounds__(128, 9)
fused_loss_kernel(const float4* __restrict__ pred,
                  const float4* __restrict__ target,
                  float* __restrict__ out) {
    const int strip = blockIdx.x;
    const int b     = blockIdx.y;
    const int w     = threadIdx.x;
    const int lane  = w & 31;
    const int wid   = w >> 5;
    const int r0    = strip * ROWS;

    const float4* t = target + b * IMG4;
    const float4* p = pred   + b * IMG4;

    __shared__ float4 sP[2][2][136];
    __shared__ float2 s_warp[2][4];
    __shared__ float  s_red[4][4];

    if (w < 16) sP[(w >> 3) & 1][(w >> 2) & 1][w & 3] = make_float4(0.f, 0.f, 0.f, 0.f);

    float acc0 = 0.f, acc1 = 0.f, acc2 = 0.f, acc3 = 0.f;

    if (strip >= 1 && strip <= STRIPS - 2) {
        run_strip<true>(t, p, r0, w, lane, wid, sP, s_warp, acc0, acc1, acc2, acc3);
    } else {
        run_strip<false>(t, p, r0, w, lane, wid, sP, s_warp, acc0, acc1, acc2, acc3);
    }

    // ---- block reduction (4 warps) ----
    float vals[4] = {acc0, acc1, acc2, acc3};
    #pragma unroll
    for (int k = 0; k < 4; ++k) {
        const float v = warp_reduce(vals[k]);
        if (lane == 0) s_red[k][wid] = v;
    }
    __syncthreads();

    if (wid == 0) {
        float v[4];
        #pragma unroll
        for (int k = 0; k < 4; ++k) {
            float vv = (lane < 4) ? s_red[k][lane] : 0.f;
            #pragma unroll
            for (int o = 2; o > 0; o >>= 1) vv += __shfl_down_sync(0xffffffffu, vv, o);
            v[k] = vv;
        }
        if (lane == 0) {
            #pragma unroll
            for (int k = 0; k < 4; ++k)
                g_part[(b * STRIPS + strip) * 4 + k] = v[k];
            __threadfence();
        }
        __syncwarp();

        unsigned int ticket = 0;
        if (lane == 0) ticket = atomicAdd(&g_ctr, 1u);
        ticket = __shfl_sync(0xffffffffu, ticket, 0);
        if (ticket == NBLOCKS - 1) {
            float wsum = 0.f, wbce_n = 0.f, inter = 0.f, uni = 0.f;
            #pragma unroll 4
            for (int s = 0; s < STRIPS; ++s) {
                const float* pp = &g_part[(lane * STRIPS + s) * 4];
                wsum   += pp[0];
                wbce_n += pp[1];
                inter  += pp[2];
                uni    += pp[3];
            }
            const float wbce = wbce_n / wsum;
            const float wiou = 1.0f - (inter + 1.0f) / (uni - inter + 1.0f);
            float loss = warp_reduce(wbce + wiou);
            if (lane == 0) {
                out[0] = loss * (1.0f / B);
                g_ctr = 0;
            }
        }
    }
}

extern "C" void kernel_launch(void* const* d_in, const int* in_sizes, int n_in,
                              void* d_out, int out_size) {
    const float4* pred   = (const float4*)d_in[0];
    const float4* target = (const float4*)d_in[1];
    float* out = (float*)d_out;

    dim3 grid(STRIPS, B);
    fused_loss_kernel<<<grid, 128>>>(pred, target, out);
}